// round 17
// baseline (speedup 1.0000x reference)
#include <cuda_runtime.h>
#include <math.h>
#include <stdint.h>

// ---------------- problem constants ----------------
#define B_SZ   8192
#define OUT_SZ 1024
#define IN_SZ  1024
#define D_SZ   4
#define NSTEPS 8
#define NROW   (B_SZ * D_SZ)          /* 32768 state rows n = b*4+d */
#define MTOT_I (OUT_SZ * D_SZ)        /* 4096 init-GEMM M */
#define EPS_N  1e-12f
#define QSCALE 16256.0f               /* 127*128 */
#define QI     (1.0f / (16256.0f * 16256.0f))

// ---------------- tiling ----------------
#define BTM  128                      /* CTA tile M */
#define BTN  128                      /* CTA tile N */
#define KCH  128                      /* k per chunk (int8) */
#define NCHUNK 8                      /* K = 1024 */
#define NTHR 256                      /* 8 warps: 4 (m) x 2 (n), warp tile 32x64 */
// stage layout (int8): Ahi 16K | Alo 16K | Bhi 16K | Blo 16K = 64KB
#define A_LO_OFF 16384
#define B_OFF    32768
#define B_LO_OFF 16384
#define STG_BYTES 65536
#define DSMEM (2 * STG_BYTES + 1024)

#define SWZ(o) ((o) ^ (((o) >> 3) & 0x70))

// ---------------- device buffers (15-bit fixed point: hi/lo int8 planes) ----
__device__ char  g_Kqh[(size_t)OUT_SZ * OUT_SZ];     // K' = tanh(coupling)+I
__device__ char  g_Kql[(size_t)OUT_SZ * OUT_SZ];
__device__ float g_SK[OUT_SZ];                       // per-row scale of K'
__device__ char  g_Wqh[(size_t)MTOT_I * IN_SZ];      // Wt [m=(o,d)][k]
__device__ char  g_Wql[(size_t)MTOT_I * IN_SZ];
__device__ float g_Sw[MTOT_I];
__device__ char  g_xqh[(size_t)B_SZ * IN_SZ];        // x [b][k]
__device__ char  g_xql[(size_t)B_SZ * IN_SZ];
__device__ float g_Sx[B_SZ];
__device__ char  g_Vqh[2][(size_t)NROW * OUT_SZ];    // state [n][j], scale 1
__device__ char  g_Vql[2][(size_t)NROW * OUT_SZ];

// ---------------- PTX helpers ----------------
__device__ __forceinline__ uint32_t smem_u32(const void* p) {
    uint32_t a;
    asm("{ .reg .u64 t; cvta.to.shared.u64 t, %1; cvt.u32.u64 %0, t; }" : "=r"(a) : "l"(p));
    return a;
}
__device__ __forceinline__ void cpasync16(uint32_t dst, const void* src) {
    asm volatile("cp.async.cg.shared.global [%0], [%1], 16;" :: "r"(dst), "l"(src));
}
#define CP_COMMIT() asm volatile("cp.async.commit_group;" ::: "memory")
#define CP_WAIT1()  asm volatile("cp.async.wait_group 1;" ::: "memory")

__device__ __forceinline__ void ldsm4(uint32_t* r, uint32_t addr) {
    asm volatile("ldmatrix.sync.aligned.m8n8.x4.shared.b16 {%0,%1,%2,%3}, [%4];"
                 : "=r"(r[0]), "=r"(r[1]), "=r"(r[2]), "=r"(r[3]) : "r"(addr));
}
// int8 MMA, k=32, exact s32 accumulate
__device__ __forceinline__ void mma_s8(int* d, const uint32_t* a, const uint32_t* b) {
    asm volatile(
        "mma.sync.aligned.m16n8k32.row.col.s32.s8.s8.s32 "
        "{%0,%1,%2,%3}, {%4,%5,%6,%7}, {%8,%9}, {%0,%1,%2,%3};"
        : "+r"(d[0]), "+r"(d[1]), "+r"(d[2]), "+r"(d[3])
        : "r"(a[0]), "r"(a[1]), "r"(a[2]), "r"(a[3]), "r"(b[0]), "r"(b[1]));
}

// quantize v (|v| <= S) into hi/lo int8: v ~= S*(128*hi+lo)/16256
__device__ __forceinline__ void quant(float v, float invS, char* ph, char* pl) {
    float u = v * invS * 127.0f;
    float h = rintf(u);
    *ph = (char)(int)h;
    *pl = (char)(int)rintf((u - h) * 128.0f);
}

// ---------------------------------------------------------------------------
// Prep kernels: one block per row; row-max scale then quantize.
// ---------------------------------------------------------------------------
__global__ void prep_kq(const float* __restrict__ coup) {
    __shared__ float red[256];
    const int i = blockIdx.x, t = threadIdx.x;
    float vals[4], vmax = 0.f;
#pragma unroll
    for (int q = 0; q < 4; q++) {
        int j = t + q * 256;
        float v = tanhf(coup[(size_t)i * 1024 + j]) + (i == j ? 1.0f : 0.0f);
        vals[q] = v;
        vmax = fmaxf(vmax, fabsf(v));
    }
    red[t] = vmax;
    __syncthreads();
    for (int off = 128; off; off >>= 1) {
        if (t < off) red[t] = fmaxf(red[t], red[t + off]);
        __syncthreads();
    }
    float S = fmaxf(red[0], 1e-30f);
    if (t == 0) g_SK[i] = S;
    float invS = 1.0f / S;
#pragma unroll
    for (int q = 0; q < 4; q++) {
        int j = t + q * 256;
        quant(vals[q], invS, &g_Kqh[(size_t)i * 1024 + j], &g_Kql[(size_t)i * 1024 + j]);
    }
}

__global__ void prep_xq(const float* __restrict__ x) {
    __shared__ float red[256];
    const int b = blockIdx.x, t = threadIdx.x;
    float vals[4], vmax = 0.f;
#pragma unroll
    for (int q = 0; q < 4; q++) {
        int k = t + q * 256;
        float v = x[(size_t)b * 1024 + k];
        vals[q] = v;
        vmax = fmaxf(vmax, fabsf(v));
    }
    red[t] = vmax;
    __syncthreads();
    for (int off = 128; off; off >>= 1) {
        if (t < off) red[t] = fmaxf(red[t], red[t + off]);
        __syncthreads();
    }
    float S = fmaxf(red[0], 1e-30f);
    if (t == 0) g_Sx[b] = S;
    float invS = 1.0f / S;
#pragma unroll
    for (int q = 0; q < 4; q++) {
        int k = t + q * 256;
        quant(vals[q], invS, &g_xqh[(size_t)b * 1024 + k], &g_xql[(size_t)b * 1024 + k]);
    }
}

// Wt row m = column m of W[k][m] (strided reads; one-time, L2-resident)
__global__ void prep_wq(const float* __restrict__ W) {
    __shared__ float red[256];
    const int m = blockIdx.x, t = threadIdx.x;
    float vals[4], vmax = 0.f;
#pragma unroll
    for (int q = 0; q < 4; q++) {
        int k = t + q * 256;
        float v = W[(size_t)k * MTOT_I + m];
        vals[q] = v;
        vmax = fmaxf(vmax, fabsf(v));
    }
    red[t] = vmax;
    __syncthreads();
    for (int off = 128; off; off >>= 1) {
        if (t < off) red[t] = fmaxf(red[t], red[t + off]);
        __syncthreads();
    }
    float S = fmaxf(red[0], 1e-30f);
    if (t == 0) g_Sw[m] = S;
    float invS = 1.0f / S;
#pragma unroll
    for (int q = 0; q < 4; q++) {
        int k = t + q * 256;
        quant(vals[q], invS, &g_Wqh[(size_t)m * 1024 + k], &g_Wql[(size_t)m * 1024 + k]);
    }
}

// ---------------------------------------------------------------------------
// Fused int8 split GEMM + normalize epilogue.
// C_int = 16384*S_hh + 128*(S_hl + S_lh)   (ll dropped; all sums exact s32)
// C = SA*SB*C_int/16256^2
// MODE 0: init   A=Wq[m][k] (Sw), B=xq[b][k] (Sx); write Vq[0][(b*4+d)][o]
// MODE 1: step   A=Vq[n][j] (S=1), B=Kq[i][j] (SK); write Vq[n][i]
// MODE 2: step final -> d_out[b][i][d] fp32
// ---------------------------------------------------------------------------
template <int MODE>
__global__ __launch_bounds__(NTHR, 1)
void gemm_s8(int sIn, const float* __restrict__ omega, float* __restrict__ out) {
    extern __shared__ char dsm_raw[];
    char* dsm = (char*)(((uintptr_t)dsm_raw + 1023) & ~(uintptr_t)1023);
    const uint32_t smemBase = smem_u32(dsm);

    const char* __restrict__ Ahq;
    const char* __restrict__ Alq;
    const char* __restrict__ Bhq;
    const char* __restrict__ Blq;
    char* __restrict__ Voh;
    char* __restrict__ Vol;
    if (MODE == 0) {
        Ahq = g_Wqh; Alq = g_Wql; Bhq = g_xqh; Blq = g_xql;
        Voh = g_Vqh[0]; Vol = g_Vql[0];
    } else {
        Ahq = g_Vqh[sIn]; Alq = g_Vql[sIn]; Bhq = g_Kqh; Blq = g_Kql;
        Voh = g_Vqh[sIn ^ 1]; Vol = g_Vql[sIn ^ 1];
    }

    const int tid = threadIdx.x;
    const int lane = tid & 31;
    const int w = tid >> 5;
    const int wm = w & 3;        // 4 m-warps of 32 rows
    const int wn = w >> 2;       // 2 n-warps of 64 cols
    const int m0 = blockIdx.y * BTM;
    const int n0 = blockIdx.x * BTN;

    // ldmatrix per-thread UNSWIZZLED base offsets (128B rows); swizzle per access.
    // 16B col unit = k16 int8; identical mapping to the fp16 k16 case.
    uint32_t aBase[2], bBase[4];
#pragma unroll
    for (int mi = 0; mi < 2; mi++) {
        int r = wm * 32 + mi * 16 + (lane & 7) + ((lane >> 3) & 1) * 8;
        int cc = (lane >> 4);
        aBase[mi] = (uint32_t)(r * 128 + cc * 16);
    }
#pragma unroll
    for (int nj = 0; nj < 4; nj++) {
        int r = wn * 64 + nj * 16 + (lane & 7) + ((lane >> 4) << 3);
        int cc = (lane >> 3) & 1;
        bBase[nj] = (uint32_t)(r * 128 + cc * 16);
    }

    int accA[2][8][4];           // S_hh
    int accB[2][8][4];           // S_hl + S_lh
#pragma unroll
    for (int a = 0; a < 2; a++)
#pragma unroll
        for (int b = 0; b < 8; b++)
#pragma unroll
            for (int c = 0; c < 4; c++) { accA[a][b][c] = 0; accB[a][b][c] = 0; }

    // chunk copy (KCH=128 int8): 4 planes of 128 rows x 128B
    auto copy_chunk = [&](int stage, int k0) {
        const uint32_t sb = smemBase + (uint32_t)(stage * STG_BYTES);
#pragma unroll
        for (int i = 0; i < 8; i++) {          // A: 2048 16B units
            int u = tid + i * NTHR;
            int sub = u >> 10;
            int r = (u & 1023) >> 3, cc = u & 7;
            const char* src = (sub ? Alq : Ahq) + (size_t)(m0 + r) * 1024 + k0 + cc * 16;
            cpasync16(sb + sub * A_LO_OFF + SWZ((uint32_t)(r * 128 + cc * 16)), src);
        }
#pragma unroll
        for (int i = 0; i < 8; i++) {          // B: 2048 16B units
            int u = tid + i * NTHR;
            int sub = u >> 10;
            int r = (u & 1023) >> 3, cc = u & 7;
            const char* src = (sub ? Blq : Bhq) + (size_t)(n0 + r) * 1024 + k0 + cc * 16;
            cpasync16(sb + B_OFF + sub * B_LO_OFF + SWZ((uint32_t)(r * 128 + cc * 16)), src);
        }
    };

    copy_chunk(0, 0);   CP_COMMIT();
    copy_chunk(1, KCH); CP_COMMIT();

    for (int c = 0; c < NCHUNK; c++) {
        CP_WAIT1();
        __syncthreads();
        const uint32_t stg = smemBase + (uint32_t)((c & 1) * STG_BYTES);

#pragma unroll
        for (int s = 0; s < 4; s++) {          // 4 k32 slices per 128B row
            const uint32_t ks = (uint32_t)(s * 32);
            uint32_t ah[2][4], al[2][4];
#pragma unroll
            for (int mi = 0; mi < 2; mi++) {
                ldsm4(ah[mi], stg + SWZ(aBase[mi] + ks));
                ldsm4(al[mi], stg + A_LO_OFF + SWZ(aBase[mi] + ks));
            }
#pragma unroll
            for (int nj = 0; nj < 4; nj++) {
                uint32_t bh[4], bl[4];
                ldsm4(bh, stg + B_OFF + SWZ(bBase[nj] + ks));
                ldsm4(bl, stg + B_OFF + B_LO_OFF + SWZ(bBase[nj] + ks));
#pragma unroll
                for (int mi = 0; mi < 2; mi++) {
                    mma_s8(accA[mi][2 * nj + 0], ah[mi], &bh[0]);
                    mma_s8(accA[mi][2 * nj + 1], ah[mi], &bh[2]);
                    mma_s8(accB[mi][2 * nj + 0], ah[mi], &bl[0]);
                    mma_s8(accB[mi][2 * nj + 1], ah[mi], &bl[2]);
                    mma_s8(accB[mi][2 * nj + 0], al[mi], &bh[0]);
                    mma_s8(accB[mi][2 * nj + 1], al[mi], &bh[2]);
                }
            }
        }

        if (c + 2 < NCHUNK) {
            __syncthreads();
            copy_chunk(c & 1, (c + 2) * KCH);
        }
        CP_COMMIT();
    }

    // ---------------- epilogue ----------------
    if (MODE == 0) {
        // rows m=(o,d), cols b. Normalize over m-quads (shfl 4,8).
#pragma unroll
        for (int mi = 0; mi < 2; mi++) {
            const int mrow = m0 + wm * 32 + mi * 16 + (lane >> 2);
#pragma unroll
            for (int fi = 0; fi < 8; fi++) {
                const int bcol = n0 + wn * 64 + fi * 8 + (lane & 3) * 2;
                const float sb0 = g_Sx[bcol], sb1 = g_Sx[bcol + 1];
#pragma unroll
                for (int h = 0; h < 2; h++) {
                    const int m = mrow + h * 8;
                    const int o = m >> 2, d = m & 3;
                    const float SA = g_Sw[m];
                    float v0 = (16384.0f * (float)accA[mi][fi][2 * h + 0] +
                                128.0f * (float)accB[mi][fi][2 * h + 0]) * (SA * sb0 * QI);
                    float v1 = (16384.0f * (float)accA[mi][fi][2 * h + 1] +
                                128.0f * (float)accB[mi][fi][2 * h + 1]) * (SA * sb1 * QI);
                    float s0 = v0 * v0, s1 = v1 * v1;
                    s0 += __shfl_xor_sync(~0u, s0, 4); s0 += __shfl_xor_sync(~0u, s0, 8);
                    s1 += __shfl_xor_sync(~0u, s1, 4); s1 += __shfl_xor_sync(~0u, s1, 8);
                    v0 *= 1.f / fmaxf(sqrtf(s0), EPS_N);
                    v1 *= 1.f / fmaxf(sqrtf(s1), EPS_N);
                    size_t p0 = (size_t)(bcol * 4 + d) * 1024 + o;
                    size_t p1 = (size_t)((bcol + 1) * 4 + d) * 1024 + o;
                    quant(v0, 1.0f, &Voh[p0], &Vol[p0]);
                    quant(v1, 1.0f, &Voh[p1], &Vol[p1]);
                }
            }
        }
    } else {
        // rows n=(b,d), cols i. Normalize over n-quads (shfl 4,8).
#pragma unroll
        for (int mi = 0; mi < 2; mi++) {
            const int nrow = m0 + wm * 32 + mi * 16 + (lane >> 2);
            const int d = nrow & 3;
#pragma unroll
            for (int fi = 0; fi < 8; fi++) {
                const int icol = n0 + wn * 64 + fi * 8 + (lane & 3) * 2;
                const float om0 = omega[icol * 4 + d];
                const float om1 = omega[icol * 4 + 4 + d];
                const float sk0 = g_SK[icol] * QI, sk1 = g_SK[icol + 1] * QI;
#pragma unroll
                for (int h = 0; h < 2; h++) {
                    const int n = nrow + h * 8;
                    float v0 = (16384.0f * (float)accA[mi][fi][2 * h + 0] +
                                128.0f * (float)accB[mi][fi][2 * h + 0]) * sk0 + om0;
                    float v1 = (16384.0f * (float)accA[mi][fi][2 * h + 1] +
                                128.0f * (float)accB[mi][fi][2 * h + 1]) * sk1 + om1;
                    float s0 = v0 * v0, s1 = v1 * v1;
                    s0 += __shfl_xor_sync(~0u, s0, 4); s0 += __shfl_xor_sync(~0u, s0, 8);
                    s1 += __shfl_xor_sync(~0u, s1, 4); s1 += __shfl_xor_sync(~0u, s1, 8);
                    v0 *= 1.f / fmaxf(sqrtf(s0), EPS_N);
                    v1 *= 1.f / fmaxf(sqrtf(s1), EPS_N);
                    if (MODE == 2) {
                        out[(size_t)(n >> 2) * 4096 + icol * 4 + d] = v0;
                        out[(size_t)(n >> 2) * 4096 + (icol + 1) * 4 + d] = v1;
                    } else {
                        char h0, l0, h1, l1;
                        quant(v0, 1.0f, &h0, &l0);
                        quant(v1, 1.0f, &h1, &l1);
                        char2 hh; hh.x = h0; hh.y = h1;
                        char2 ll; ll.x = l0; ll.y = l1;
                        *(char2*)(Voh + (size_t)n * 1024 + icol) = hh;
                        *(char2*)(Vol + (size_t)n * 1024 + icol) = ll;
                    }
                }
            }
        }
    }
}

// ---------------------------------------------------------------------------
// Launch
// ---------------------------------------------------------------------------
extern "C" void kernel_launch(void* const* d_in, const int* in_sizes, int n_in,
                              void* d_out, int out_size) {
    const float* x     = (const float*)d_in[0];   // [B, IN]
    const float* W_in  = (const float*)d_in[1];   // [IN, OUT, D]
    const float* omega = (const float*)d_in[2];   // [OUT, D]
    const float* coup  = (const float*)d_in[3];   // [OUT, OUT]
    float* out = (float*)d_out;                   // [B, OUT, D]

    cudaFuncSetAttribute(gemm_s8<0>, cudaFuncAttributeMaxDynamicSharedMemorySize, DSMEM);
    cudaFuncSetAttribute(gemm_s8<1>, cudaFuncAttributeMaxDynamicSharedMemorySize, DSMEM);
    cudaFuncSetAttribute(gemm_s8<2>, cudaFuncAttributeMaxDynamicSharedMemorySize, DSMEM);

    prep_kq<<<OUT_SZ, 256>>>(coup);
    prep_xq<<<B_SZ, 256>>>(x);
    prep_wq<<<MTOT_I, 256>>>(W_in);

    // init: M = 4096 (m=(o,d)), N = 8192 (b)
    gemm_s8<0><<<dim3(B_SZ / BTN, MTOT_I / BTM), NTHR, DSMEM>>>(0, omega, out);

    // steps: M = 32768 (n rows), N = 1024 (i); x-dim (i blocks) fastest
    dim3 sgrid(OUT_SZ / BTN, NROW / BTM);
    int s = 0;
    for (int t = 0; t < NSTEPS - 1; t++) {
        gemm_s8<1><<<sgrid, NTHR, DSMEM>>>(s, omega, out);
        s ^= 1;
    }
    gemm_s8<2><<<sgrid, NTHR, DSMEM>>>(s, omega, out);
}